// round 7
// baseline (speedup 1.0000x reference)
#include <cuda_runtime.h>
#include <cuda_fp16.h>

#define MAX_NODES  75008
#define MAX_EDGES  1200128
#define F  64
#define F4 (F / 4)
#define SCAN_B 1024
#define MAX_SCAN_BLOCKS 256

// __device__ scratch (allocation-free rule)
__device__ int   g_offset[MAX_NODES];       // CSR start per node
__device__ int   g_cursor[MAX_NODES];       // atomic fill cursor
__device__ float g_inv[MAX_NODES];          // rsqrt(degree)
__device__ int   g_blocksum[MAX_SCAN_BLOCKS];
__device__ int   g_sorted[MAX_EDGES];       // src ids bucketed by dst
__device__ uint4 g_P[MAX_NODES * 8];        // fp16 messages: 8 x uint4 = 64 halves/row
__device__ float g_agg[MAX_NODES * F];

// count[n] = round(degree[n]) - 1  (degree = indeg + 1 -> free histogram)
__device__ __forceinline__ int node_count(const float* degree, int i, int N) {
    return (i < N) ? (__float2int_rn(degree[i]) - 1) : 0;
}

__device__ __forceinline__ int warp_incl_scan(int v) {
    #pragma unroll
    for (int o = 1; o < 32; o <<= 1) {
        int u = __shfl_up_sync(0xffffffffu, v, o);
        if ((threadIdx.x & 31) >= o) v += u;
    }
    return v;
}

// scan pass 1: per-block sums of counts
__global__ void scan1_kernel(const float* __restrict__ degree, int N) {
    int i = blockIdx.x * SCAN_B + threadIdx.x;
    int c = node_count(degree, i, N);
    int w = __reduce_add_sync(0xffffffffu, c);
    __shared__ int ws[32];
    if ((threadIdx.x & 31) == 0) ws[threadIdx.x >> 5] = w;
    __syncthreads();
    if (threadIdx.x < 32) {
        int v = (threadIdx.x < (SCAN_B / 32)) ? ws[threadIdx.x] : 0;
        v = __reduce_add_sync(0xffffffffu, v);
        if (threadIdx.x == 0) g_blocksum[blockIdx.x] = v;
    }
}

// scan pass 2: exclusive scan of block sums (single block)
__global__ void scan2_kernel(int nb) {
    __shared__ int s[MAX_SCAN_BLOCKS];
    int tid = threadIdx.x;
    int v = (tid < nb) ? g_blocksum[tid] : 0;
    s[tid] = v;
    __syncthreads();
    #pragma unroll
    for (int o = 1; o < MAX_SCAN_BLOCKS; o <<= 1) {
        int u = (tid >= o) ? s[tid - o] : 0;
        __syncthreads();
        s[tid] += u;
        __syncthreads();
    }
    if (tid < nb) g_blocksum[tid] = s[tid] - v;   // exclusive
}

// scan pass 3: offsets + cursors + rsqrt(degree)
__global__ void scan3_kernel(const float* __restrict__ degree, int N) {
    int tid = threadIdx.x;
    int i = blockIdx.x * SCAN_B + tid;
    int c = node_count(degree, i, N);

    int lane = tid & 31, wid = tid >> 5;
    int incl = warp_incl_scan(c);
    __shared__ int ws[32];
    if (lane == 31) ws[wid] = incl;
    __syncthreads();
    if (wid == 0) {
        int v = (lane < (SCAN_B / 32)) ? ws[lane] : 0;
        v = warp_incl_scan(v);
        ws[lane] = v;
    }
    __syncthreads();
    int base = (wid ? ws[wid - 1] : 0) + g_blocksum[blockIdx.x];
    int excl = base + incl - c;
    if (i < N) {
        g_offset[i] = excl;
        g_cursor[i] = excl;
        g_inv[i]    = rsqrtf(degree[i]);
    }
}

// FUSED bucket + prescale. Bucket is atomic-latency bound (issue < 5%);
// prescale is coalesced DRAM streaming. Disjoint resources, no dependence
// between the two -> prescale hides in bucket's latency shadow.
__global__ void bucket_prescale_kernel(const float* __restrict__ feature,
                                       const float* __restrict__ degree,
                                       const int*   __restrict__ src,
                                       const int*   __restrict__ dst,
                                       int E, int N) {
    int t = blockIdx.x * blockDim.x + threadIdx.x;

    // prescale: P[n] = fp16(feature[n] * rsqrt(degree[n])), 8 threads/row
    if (t < N * 8) {
        int node = t >> 3;
        int c = t & 7;
        float s = rsqrtf(__ldg(degree + node));
        const float4* frow =
            reinterpret_cast<const float4*>(feature) + node * F4 + c * 2;
        float4 a = __ldg(frow);
        float4 b = __ldg(frow + 1);

        __half2 h0 = __floats2half2_rn(a.x * s, a.y * s);
        __half2 h1 = __floats2half2_rn(a.z * s, a.w * s);
        __half2 h2 = __floats2half2_rn(b.x * s, b.y * s);
        __half2 h3 = __floats2half2_rn(b.z * s, b.w * s);

        uint4 p;
        p.x = *reinterpret_cast<unsigned*>(&h0);
        p.y = *reinterpret_cast<unsigned*>(&h1);
        p.z = *reinterpret_cast<unsigned*>(&h2);
        p.w = *reinterpret_cast<unsigned*>(&h3);
        g_P[node * 8 + c] = p;
    }

    // bucket: scalar per-edge (R4 showed per-thread ILP regresses here)
    if (t < E) {
        int d = __ldg(dst + t);
        int pos = atomicAdd(&g_cursor[d], 1);
        g_sorted[pos] = __ldg(src + t);
    }
}

// gather: ONE WARP PER NODE, 4 edge-groups of 8 lanes. Group g handles
// edges g, g+4, g+8, ... -> 4 independent 128B-row streams per warp
// (x unroll 2 = 8 in flight), no cross-node lockstep divergence.
// Epilogue: shfl-fold the 4 groups, lanes 0-7 store the fp32 row.
__global__ void __launch_bounds__(256)
gather_kernel(const float* __restrict__ degree, int N) {
    int warp = (blockIdx.x * blockDim.x + threadIdx.x) >> 5;
    if (warp >= N) return;
    int lane = threadIdx.x & 31;
    int g = lane >> 3;        // edge group 0..3
    int c = lane & 7;         // 16B column chunk within row

    int start = g_offset[warp];
    int cnt = __float2int_rn(__ldg(degree + warp)) - 1;

    float acc[8] = {0.f, 0.f, 0.f, 0.f, 0.f, 0.f, 0.f, 0.f};

    #pragma unroll 2
    for (int i = g; i < cnt; i += 4) {
        int s = __ldg(g_sorted + start + i);        // broadcast within group
        uint4 p = g_P[s * 8 + c];                   // 128B/row, 4 rows/warp
        __half2 h0 = *reinterpret_cast<__half2*>(&p.x);
        __half2 h1 = *reinterpret_cast<__half2*>(&p.y);
        __half2 h2 = *reinterpret_cast<__half2*>(&p.z);
        __half2 h3 = *reinterpret_cast<__half2*>(&p.w);
        float2 f0 = __half22float2(h0);
        float2 f1 = __half22float2(h1);
        float2 f2 = __half22float2(h2);
        float2 f3 = __half22float2(h3);
        acc[0] += f0.x; acc[1] += f0.y;
        acc[2] += f1.x; acc[3] += f1.y;
        acc[4] += f2.x; acc[5] += f2.y;
        acc[6] += f3.x; acc[7] += f3.y;
    }

    // fold groups 3->1, 2->0 then 1->0 (lanes 0-7 end with node totals)
    #pragma unroll
    for (int j = 0; j < 8; j++) {
        acc[j] += __shfl_down_sync(0xffffffffu, acc[j], 16);
        acc[j] += __shfl_down_sync(0xffffffffu, acc[j], 8);
    }

    if (g == 0) {
        float4* orow = reinterpret_cast<float4*>(g_agg + warp * F + c * 8);
        orow[0] = make_float4(acc[0], acc[1], acc[2], acc[3]);
        orow[1] = make_float4(acc[4], acc[5], acc[6], acc[7]);
    }
}

// node apply: out[n] = (agg[n] * g_inv[n]) @ W + b. FFMA-roofline.
__global__ void __launch_bounds__(256)
gemm_kernel(const float* __restrict__ W,
            const float* __restrict__ b,
            float* __restrict__ out, int N) {
    __shared__ float4 Ws[F * F4];
    __shared__ float4 bs[F4];

    for (int i = threadIdx.x; i < F * F4; i += blockDim.x)
        Ws[i] = reinterpret_cast<const float4*>(W)[i];
    if (threadIdx.x < F4)
        bs[threadIdx.x] = reinterpret_cast<const float4*>(b)[threadIdx.x];
    __syncthreads();

    int row = blockIdx.x * blockDim.x + threadIdx.x;
    if (row >= N) return;

    float acc[F];
    #pragma unroll
    for (int j = 0; j < F4; j++) {
        float4 bb = bs[j];
        acc[4 * j + 0] = bb.x; acc[4 * j + 1] = bb.y;
        acc[4 * j + 2] = bb.z; acc[4 * j + 3] = bb.w;
    }

    float s = g_inv[row];
    const float4* arow = reinterpret_cast<const float4*>(g_agg + (long)row * F);

    #pragma unroll 4
    for (int k4 = 0; k4 < F4; k4++) {
        float4 hv = __ldg(arow + k4);
        hv.x *= s; hv.y *= s; hv.z *= s; hv.w *= s;
        #pragma unroll
        for (int kk = 0; kk < 4; kk++) {
            float h = (kk == 0) ? hv.x : (kk == 1) ? hv.y : (kk == 2) ? hv.z : hv.w;
            int k = k4 * 4 + kk;
            #pragma unroll
            for (int j = 0; j < F4; j++) {
                float4 w = Ws[k * F4 + j];       // warp-uniform smem broadcast
                acc[4 * j + 0] += h * w.x;
                acc[4 * j + 1] += h * w.y;
                acc[4 * j + 2] += h * w.z;
                acc[4 * j + 3] += h * w.w;
            }
        }
    }

    float4* orow = reinterpret_cast<float4*>(out + (long)row * F);
    #pragma unroll
    for (int j = 0; j < F4; j++)
        orow[j] = make_float4(acc[4 * j + 0], acc[4 * j + 1],
                              acc[4 * j + 2], acc[4 * j + 3]);
}

// ---------------------------------------------------------------------------
extern "C" void kernel_launch(void* const* d_in, const int* in_sizes, int n_in,
                              void* d_out, int out_size) {
    const float* feature = (const float*)d_in[0];
    const float* degree  = (const float*)d_in[1];
    const int*   src     = (const int*)d_in[2];
    const int*   dst     = (const int*)d_in[3];
    const float* W       = (const float*)d_in[4];
    const float* b       = (const float*)d_in[5];
    float*       out     = (float*)d_out;

    int N = in_sizes[1];
    int E = in_sizes[2];
    int nb = (N + SCAN_B - 1) / SCAN_B;

    scan1_kernel<<<nb, SCAN_B>>>(degree, N);
    scan2_kernel<<<1, MAX_SCAN_BLOCKS>>>(nb);
    scan3_kernel<<<nb, SCAN_B>>>(degree, N);

    int fthreads = (E > N * 8) ? E : N * 8;
    bucket_prescale_kernel<<<(fthreads + 255) / 256, 256>>>(
        feature, degree, src, dst, E, N);

    long long gthreads = (long long)N * 32;
    gather_kernel<<<(int)((gthreads + 255) / 256), 256>>>(degree, N);

    gemm_kernel<<<(N + 255) / 256, 256>>>(W, b, out, N);
}

// round 8
// speedup vs baseline: 1.0033x; 1.0033x over previous
#include <cuda_runtime.h>
#include <cuda_fp16.h>

#define MAX_NODES  75008
#define MAX_EDGES  1200128
#define F  64
#define F4 (F / 4)
#define SCAN_B 1024
#define MAX_SCAN_BLOCKS 256

// __device__ scratch (allocation-free rule)
__device__ int   g_offset[MAX_NODES];       // CSR start per node
__device__ int   g_cursor[MAX_NODES];       // atomic fill cursor
__device__ float g_inv[MAX_NODES];          // rsqrt(degree)
__device__ int   g_blocksum[MAX_SCAN_BLOCKS];
__device__ int   g_sorted[MAX_EDGES];       // src ids bucketed by dst
__device__ uint4 g_P[MAX_NODES * 8];        // fp16 messages: 8 x uint4 = 64 halves/row
__device__ float g_agg[MAX_NODES * F];

// count[n] = round(degree[n]) - 1  (degree = indeg + 1 -> free histogram)
__device__ __forceinline__ int node_count(const float* degree, int i, int N) {
    return (i < N) ? (__float2int_rn(degree[i]) - 1) : 0;
}

__device__ __forceinline__ int warp_incl_scan(int v) {
    #pragma unroll
    for (int o = 1; o < 32; o <<= 1) {
        int u = __shfl_up_sync(0xffffffffu, v, o);
        if ((threadIdx.x & 31) >= o) v += u;
    }
    return v;
}

// scan pass 1: per-block sums of counts
__global__ void scan1_kernel(const float* __restrict__ degree, int N) {
    int i = blockIdx.x * SCAN_B + threadIdx.x;
    int c = node_count(degree, i, N);
    int w = __reduce_add_sync(0xffffffffu, c);
    __shared__ int ws[32];
    if ((threadIdx.x & 31) == 0) ws[threadIdx.x >> 5] = w;
    __syncthreads();
    if (threadIdx.x < 32) {
        int v = (threadIdx.x < (SCAN_B / 32)) ? ws[threadIdx.x] : 0;
        v = __reduce_add_sync(0xffffffffu, v);
        if (threadIdx.x == 0) g_blocksum[blockIdx.x] = v;
    }
}

// scan pass 2: exclusive scan of block sums (single block)
__global__ void scan2_kernel(int nb) {
    __shared__ int s[MAX_SCAN_BLOCKS];
    int tid = threadIdx.x;
    int v = (tid < nb) ? g_blocksum[tid] : 0;
    s[tid] = v;
    __syncthreads();
    #pragma unroll
    for (int o = 1; o < MAX_SCAN_BLOCKS; o <<= 1) {
        int u = (tid >= o) ? s[tid - o] : 0;
        __syncthreads();
        s[tid] += u;
        __syncthreads();
    }
    if (tid < nb) g_blocksum[tid] = s[tid] - v;   // exclusive
}

// scan pass 3: offsets + cursors + rsqrt(degree)
__global__ void scan3_kernel(const float* __restrict__ degree, int N) {
    int tid = threadIdx.x;
    int i = blockIdx.x * SCAN_B + tid;
    int c = node_count(degree, i, N);

    int lane = tid & 31, wid = tid >> 5;
    int incl = warp_incl_scan(c);
    __shared__ int ws[32];
    if (lane == 31) ws[wid] = incl;
    __syncthreads();
    if (wid == 0) {
        int v = (lane < (SCAN_B / 32)) ? ws[lane] : 0;
        v = warp_incl_scan(v);
        ws[lane] = v;
    }
    __syncthreads();
    int base = (wid ? ws[wid - 1] : 0) + g_blocksum[blockIdx.x];
    int excl = base + incl - c;
    if (i < N) {
        g_offset[i] = excl;
        g_cursor[i] = excl;
        g_inv[i]    = rsqrtf(degree[i]);
    }
}

// FUSED bucket + prescale. Bucket is atomic-latency bound (issue < 5%);
// prescale is coalesced DRAM streaming. Disjoint resources, no dependence
// between the two -> prescale hides in bucket's latency shadow.
__global__ void bucket_prescale_kernel(const float* __restrict__ feature,
                                       const float* __restrict__ degree,
                                       const int*   __restrict__ src,
                                       const int*   __restrict__ dst,
                                       int E, int N) {
    int t = blockIdx.x * blockDim.x + threadIdx.x;

    // prescale: P[n] = fp16(feature[n] * rsqrt(degree[n])), 8 threads/row
    if (t < N * 8) {
        int node = t >> 3;
        int c = t & 7;
        float s = rsqrtf(__ldg(degree + node));
        const float4* frow =
            reinterpret_cast<const float4*>(feature) + node * F4 + c * 2;
        float4 a = __ldg(frow);
        float4 b = __ldg(frow + 1);

        __half2 h0 = __floats2half2_rn(a.x * s, a.y * s);
        __half2 h1 = __floats2half2_rn(a.z * s, a.w * s);
        __half2 h2 = __floats2half2_rn(b.x * s, b.y * s);
        __half2 h3 = __floats2half2_rn(b.z * s, b.w * s);

        uint4 p;
        p.x = *reinterpret_cast<unsigned*>(&h0);
        p.y = *reinterpret_cast<unsigned*>(&h1);
        p.z = *reinterpret_cast<unsigned*>(&h2);
        p.w = *reinterpret_cast<unsigned*>(&h3);
        g_P[node * 8 + c] = p;
    }

    // bucket: scalar per-edge (R4 showed per-thread ILP regresses here)
    if (t < E) {
        int d = __ldg(dst + t);
        int pos = atomicAdd(&g_cursor[d], 1);
        g_sorted[pos] = __ldg(src + t);
    }
}

// gather: ONE WARP PER NODE, 4 edge-groups of 8 lanes. Group g handles
// edges g, g+4, g+8, ... -> 4 independent 128B-row streams per warp
// (x unroll 2 = 8 in flight), no cross-node lockstep divergence.
// Epilogue: shfl-fold the 4 groups, lanes 0-7 store the fp32 row.
__global__ void __launch_bounds__(256)
gather_kernel(const float* __restrict__ degree, int N) {
    int warp = (blockIdx.x * blockDim.x + threadIdx.x) >> 5;
    if (warp >= N) return;
    int lane = threadIdx.x & 31;
    int g = lane >> 3;        // edge group 0..3
    int c = lane & 7;         // 16B column chunk within row

    int start = g_offset[warp];
    int cnt = __float2int_rn(__ldg(degree + warp)) - 1;

    float acc[8] = {0.f, 0.f, 0.f, 0.f, 0.f, 0.f, 0.f, 0.f};

    #pragma unroll 2
    for (int i = g; i < cnt; i += 4) {
        int s = __ldg(g_sorted + start + i);        // broadcast within group
        uint4 p = g_P[s * 8 + c];                   // 128B/row, 4 rows/warp
        __half2 h0 = *reinterpret_cast<__half2*>(&p.x);
        __half2 h1 = *reinterpret_cast<__half2*>(&p.y);
        __half2 h2 = *reinterpret_cast<__half2*>(&p.z);
        __half2 h3 = *reinterpret_cast<__half2*>(&p.w);
        float2 f0 = __half22float2(h0);
        float2 f1 = __half22float2(h1);
        float2 f2 = __half22float2(h2);
        float2 f3 = __half22float2(h3);
        acc[0] += f0.x; acc[1] += f0.y;
        acc[2] += f1.x; acc[3] += f1.y;
        acc[4] += f2.x; acc[5] += f2.y;
        acc[6] += f3.x; acc[7] += f3.y;
    }

    // fold groups 3->1, 2->0 then 1->0 (lanes 0-7 end with node totals)
    #pragma unroll
    for (int j = 0; j < 8; j++) {
        acc[j] += __shfl_down_sync(0xffffffffu, acc[j], 16);
        acc[j] += __shfl_down_sync(0xffffffffu, acc[j], 8);
    }

    if (g == 0) {
        float4* orow = reinterpret_cast<float4*>(g_agg + warp * F + c * 8);
        orow[0] = make_float4(acc[0], acc[1], acc[2], acc[3]);
        orow[1] = make_float4(acc[4], acc[5], acc[6], acc[7]);
    }
}

// node apply: out[n] = (agg[n] * g_inv[n]) @ W + b. FFMA-roofline.
__global__ void __launch_bounds__(256)
gemm_kernel(const float* __restrict__ W,
            const float* __restrict__ b,
            float* __restrict__ out, int N) {
    __shared__ float4 Ws[F * F4];
    __shared__ float4 bs[F4];

    for (int i = threadIdx.x; i < F * F4; i += blockDim.x)
        Ws[i] = reinterpret_cast<const float4*>(W)[i];
    if (threadIdx.x < F4)
        bs[threadIdx.x] = reinterpret_cast<const float4*>(b)[threadIdx.x];
    __syncthreads();

    int row = blockIdx.x * blockDim.x + threadIdx.x;
    if (row >= N) return;

    float acc[F];
    #pragma unroll
    for (int j = 0; j < F4; j++) {
        float4 bb = bs[j];
        acc[4 * j + 0] = bb.x; acc[4 * j + 1] = bb.y;
        acc[4 * j + 2] = bb.z; acc[4 * j + 3] = bb.w;
    }

    float s = g_inv[row];
    const float4* arow = reinterpret_cast<const float4*>(g_agg + (long)row * F);

    #pragma unroll 4
    for (int k4 = 0; k4 < F4; k4++) {
        float4 hv = __ldg(arow + k4);
        hv.x *= s; hv.y *= s; hv.z *= s; hv.w *= s;
        #pragma unroll
        for (int kk = 0; kk < 4; kk++) {
            float h = (kk == 0) ? hv.x : (kk == 1) ? hv.y : (kk == 2) ? hv.z : hv.w;
            int k = k4 * 4 + kk;
            #pragma unroll
            for (int j = 0; j < F4; j++) {
                float4 w = Ws[k * F4 + j];       // warp-uniform smem broadcast
                acc[4 * j + 0] += h * w.x;
                acc[4 * j + 1] += h * w.y;
                acc[4 * j + 2] += h * w.z;
                acc[4 * j + 3] += h * w.w;
            }
        }
    }

    float4* orow = reinterpret_cast<float4*>(out + (long)row * F);
    #pragma unroll
    for (int j = 0; j < F4; j++)
        orow[j] = make_float4(acc[4 * j + 0], acc[4 * j + 1],
                              acc[4 * j + 2], acc[4 * j + 3]);
}

// ---------------------------------------------------------------------------
extern "C" void kernel_launch(void* const* d_in, const int* in_sizes, int n_in,
                              void* d_out, int out_size) {
    const float* feature = (const float*)d_in[0];
    const float* degree  = (const float*)d_in[1];
    const int*   src     = (const int*)d_in[2];
    const int*   dst     = (const int*)d_in[3];
    const float* W       = (const float*)d_in[4];
    const float* b       = (const float*)d_in[5];
    float*       out     = (float*)d_out;

    int N = in_sizes[1];
    int E = in_sizes[2];
    int nb = (N + SCAN_B - 1) / SCAN_B;

    scan1_kernel<<<nb, SCAN_B>>>(degree, N);
    scan2_kernel<<<1, MAX_SCAN_BLOCKS>>>(nb);
    scan3_kernel<<<nb, SCAN_B>>>(degree, N);

    int fthreads = (E > N * 8) ? E : N * 8;
    bucket_prescale_kernel<<<(fthreads + 255) / 256, 256>>>(
        feature, degree, src, dst, E, N);

    long long gthreads = (long long)N * 32;
    gather_kernel<<<(int)((gthreads + 255) / 256), 256>>>(degree, N);

    gemm_kernel<<<(N + 255) / 256, 256>>>(W, b, out, N);
}

// round 9
// speedup vs baseline: 1.0550x; 1.0516x over previous
#include <cuda_runtime.h>
#include <cuda_fp16.h>

#define MAX_NODES  75008
#define MAX_EDGES  1200128
#define F  64
#define F4 (F / 4)
#define SCAN_B 1024
#define MAX_SCAN_BLOCKS 256

// __device__ scratch (allocation-free rule)
__device__ int   g_offset[MAX_NODES];       // CSR start per node
__device__ int   g_cursor[MAX_NODES];       // atomic fill cursor
__device__ float g_inv[MAX_NODES];          // rsqrt(degree)
__device__ int   g_blocksum[MAX_SCAN_BLOCKS];
__device__ int   g_sorted[MAX_EDGES];       // src ids bucketed by dst
__device__ uint4 g_P[MAX_NODES * 8];        // fp16 messages: 8 x uint4 = 64 halves/row
__device__ float g_agg[MAX_NODES * F];

__device__ __forceinline__ int node_count(const float* degree, int i, int N) {
    return (i < N) ? (__float2int_rn(degree[i]) - 1) : 0;   // degree = indeg+1
}

__device__ __forceinline__ int warp_incl_scan(int v) {
    #pragma unroll
    for (int o = 1; o < 32; o <<= 1) {
        int u = __shfl_up_sync(0xffffffffu, v, o);
        if ((threadIdx.x & 31) >= o) v += u;
    }
    return v;
}

__global__ void scan1_kernel(const float* __restrict__ degree, int N) {
    int i = blockIdx.x * SCAN_B + threadIdx.x;
    int c = node_count(degree, i, N);
    int w = __reduce_add_sync(0xffffffffu, c);
    __shared__ int ws[32];
    if ((threadIdx.x & 31) == 0) ws[threadIdx.x >> 5] = w;
    __syncthreads();
    if (threadIdx.x < 32) {
        int v = (threadIdx.x < (SCAN_B / 32)) ? ws[threadIdx.x] : 0;
        v = __reduce_add_sync(0xffffffffu, v);
        if (threadIdx.x == 0) g_blocksum[blockIdx.x] = v;
    }
}

__global__ void scan2_kernel(int nb) {
    __shared__ int s[MAX_SCAN_BLOCKS];
    int tid = threadIdx.x;
    int v = (tid < nb) ? g_blocksum[tid] : 0;
    s[tid] = v;
    __syncthreads();
    #pragma unroll
    for (int o = 1; o < MAX_SCAN_BLOCKS; o <<= 1) {
        int u = (tid >= o) ? s[tid - o] : 0;
        __syncthreads();
        s[tid] += u;
        __syncthreads();
    }
    if (tid < nb) g_blocksum[tid] = s[tid] - v;   // exclusive
}

__global__ void scan3_kernel(const float* __restrict__ degree, int N) {
    int tid = threadIdx.x;
    int i = blockIdx.x * SCAN_B + tid;
    int c = node_count(degree, i, N);

    int lane = tid & 31, wid = tid >> 5;
    int incl = warp_incl_scan(c);
    __shared__ int ws[32];
    if (lane == 31) ws[wid] = incl;
    __syncthreads();
    if (wid == 0) {
        int v = (lane < (SCAN_B / 32)) ? ws[lane] : 0;
        v = warp_incl_scan(v);
        ws[lane] = v;
    }
    __syncthreads();
    int base = (wid ? ws[wid - 1] : 0) + g_blocksum[blockIdx.x];
    int excl = base + incl - c;
    if (i < N) {
        g_offset[i] = excl;
        g_cursor[i] = excl;
        g_inv[i]    = rsqrtf(degree[i]);
    }
}

// FUSED bucket + prescale (R8: 21.9us vs 26.5 split — keep).
__global__ void bucket_prescale_kernel(const float* __restrict__ feature,
                                       const float* __restrict__ degree,
                                       const int*   __restrict__ src,
                                       const int*   __restrict__ dst,
                                       int E, int N) {
    int t = blockIdx.x * blockDim.x + threadIdx.x;

    if (t < N * 8) {          // prescale: P[n] = fp16(feature[n]*rsqrt(deg[n]))
        int node = t >> 3;
        int c = t & 7;
        float s = rsqrtf(__ldg(degree + node));
        const float4* frow =
            reinterpret_cast<const float4*>(feature) + node * F4 + c * 2;
        float4 a = __ldg(frow);
        float4 b = __ldg(frow + 1);

        __half2 h0 = __floats2half2_rn(a.x * s, a.y * s);
        __half2 h1 = __floats2half2_rn(a.z * s, a.w * s);
        __half2 h2 = __floats2half2_rn(b.x * s, b.y * s);
        __half2 h3 = __floats2half2_rn(b.z * s, b.w * s);

        uint4 p;
        p.x = *reinterpret_cast<unsigned*>(&h0);
        p.y = *reinterpret_cast<unsigned*>(&h1);
        p.z = *reinterpret_cast<unsigned*>(&h2);
        p.w = *reinterpret_cast<unsigned*>(&h3);
        g_P[node * 8 + c] = p;
    }

    if (t < E) {              // bucket: scalar per-edge
        int d = __ldg(dst + t);
        int pos = atomicAdd(&g_cursor[d], 1);
        g_sorted[pos] = __ldg(src + t);
    }
}

// gather — R6 layout (measured best): 8 lanes/node, lane owns one uint4
// (8 halves); sequential edge loop, unroll 4 -> 16 independent row loads
// in flight per warp. fp32 accumulation, plain stores.
__global__ void __launch_bounds__(256)
gather_kernel(const float* __restrict__ degree, int N) {
    int t = blockIdx.x * blockDim.x + threadIdx.x;
    int node = t >> 3;
    int c = t & 7;
    if (node >= N) return;

    int start = g_offset[node];
    int cnt = __float2int_rn(__ldg(degree + node)) - 1;

    float acc[8] = {0.f, 0.f, 0.f, 0.f, 0.f, 0.f, 0.f, 0.f};

    #pragma unroll 4
    for (int i = 0; i < cnt; i++) {
        int s = __ldg(g_sorted + start + i);        // broadcast across 8 lanes
        uint4 p = g_P[s * 8 + c];
        __half2 h0 = *reinterpret_cast<__half2*>(&p.x);
        __half2 h1 = *reinterpret_cast<__half2*>(&p.y);
        __half2 h2 = *reinterpret_cast<__half2*>(&p.z);
        __half2 h3 = *reinterpret_cast<__half2*>(&p.w);
        float2 f0 = __half22float2(h0);
        float2 f1 = __half22float2(h1);
        float2 f2 = __half22float2(h2);
        float2 f3 = __half22float2(h3);
        acc[0] += f0.x; acc[1] += f0.y;
        acc[2] += f1.x; acc[3] += f1.y;
        acc[4] += f2.x; acc[5] += f2.y;
        acc[6] += f3.x; acc[7] += f3.y;
    }

    float4* orow = reinterpret_cast<float4*>(g_agg + node * F + c * 8);
    orow[0] = make_float4(acc[0], acc[1], acc[2], acc[3]);
    orow[1] = make_float4(acc[4], acc[5], acc[6], acc[7]);
}

// node apply with PACKED f32x2 FFMA (FFMA2): 3-reg FFMA runs at rt=2/SMSP
// (64 lanes/cyc/SM) -> 18us floor; fma.rn.f32x2 halves instruction count.
// ptxas never auto-fuses this; PTX-only.
__global__ void __launch_bounds__(256)
gemm_kernel(const float* __restrict__ W,
            const float* __restrict__ b,
            float* __restrict__ out, int N) {
    __shared__ float4 Ws[F * F4];     // W[k][j4]
    __shared__ float4 bs[F4];

    for (int i = threadIdx.x; i < F * F4; i += blockDim.x)
        Ws[i] = reinterpret_cast<const float4*>(W)[i];
    if (threadIdx.x < F4)
        bs[threadIdx.x] = reinterpret_cast<const float4*>(b)[threadIdx.x];
    __syncthreads();

    int row = blockIdx.x * blockDim.x + threadIdx.x;
    if (row >= N) return;

    // 32 packed accumulators (j pairs)
    unsigned long long acc[F / 2];
    #pragma unroll
    for (int j = 0; j < F4; j++) {
        float4 bb = bs[j];
        asm("mov.b64 %0, {%1, %2};" : "=l"(acc[2 * j + 0]) : "f"(bb.x), "f"(bb.y));
        asm("mov.b64 %0, {%1, %2};" : "=l"(acc[2 * j + 1]) : "f"(bb.z), "f"(bb.w));
    }

    float s = g_inv[row];
    const float4* arow = reinterpret_cast<const float4*>(g_agg + (long)row * F);

    #pragma unroll 4
    for (int k4 = 0; k4 < F4; k4++) {
        float4 hv = __ldg(arow + k4);
        hv.x *= s; hv.y *= s; hv.z *= s; hv.w *= s;
        #pragma unroll
        for (int kk = 0; kk < 4; kk++) {
            float h = (kk == 0) ? hv.x : (kk == 1) ? hv.y : (kk == 2) ? hv.z : hv.w;
            unsigned long long h2;
            asm("mov.b64 %0, {%1, %1};" : "=l"(h2) : "f"(h));   // (h, h)
            int k = k4 * 4 + kk;
            #pragma unroll
            for (int j = 0; j < F4; j++) {
                float4 w = Ws[k * F4 + j];       // warp-uniform smem broadcast
                unsigned long long w01, w23;
                asm("mov.b64 %0, {%1, %2};" : "=l"(w01) : "f"(w.x), "f"(w.y));
                asm("mov.b64 %0, {%1, %2};" : "=l"(w23) : "f"(w.z), "f"(w.w));
                asm("fma.rn.f32x2 %0, %1, %2, %0;"
                    : "+l"(acc[2 * j + 0]) : "l"(h2), "l"(w01));
                asm("fma.rn.f32x2 %0, %1, %2, %0;"
                    : "+l"(acc[2 * j + 1]) : "l"(h2), "l"(w23));
            }
        }
    }

    float4* orow = reinterpret_cast<float4*>(out + (long)row * F);
    #pragma unroll
    for (int j = 0; j < F4; j++) {
        float x, y, z, w;
        asm("mov.b64 {%0, %1}, %2;" : "=f"(x), "=f"(y) : "l"(acc[2 * j + 0]));
        asm("mov.b64 {%0, %1}, %2;" : "=f"(z), "=f"(w) : "l"(acc[2 * j + 1]));
        orow[j] = make_float4(x, y, z, w);
    }
}

// ---------------------------------------------------------------------------
extern "C" void kernel_launch(void* const* d_in, const int* in_sizes, int n_in,
                              void* d_out, int out_size) {
    const float* feature = (const float*)d_in[0];
    const float* degree  = (const float*)d_in[1];
    const int*   src     = (const int*)d_in[2];
    const int*   dst     = (const int*)d_in[3];
    const float* W       = (const float*)d_in[4];
    const float* b       = (const float*)d_in[5];
    float*       out     = (float*)d_out;

    int N = in_sizes[1];
    int E = in_sizes[2];
    int nb = (N + SCAN_B - 1) / SCAN_B;

    scan1_kernel<<<nb, SCAN_B>>>(degree, N);
    scan2_kernel<<<1, MAX_SCAN_BLOCKS>>>(nb);
    scan3_kernel<<<nb, SCAN_B>>>(degree, N);

    int fthreads = (E > N * 8) ? E : N * 8;
    bucket_prescale_kernel<<<(fthreads + 255) / 256, 256>>>(
        feature, degree, src, dst, E, N);

    int gthreads = N * 8;
    gather_kernel<<<(gthreads + 255) / 256, 256>>>(degree, N);

    gemm_kernel<<<(N + 255) / 256, 256>>>(W, b, out, N);
}